// round 2
// baseline (speedup 1.0000x reference)
#include <cuda_runtime.h>
#include <cstdint>
#include <cstddef>

#define C_DIM 256
#define H_DIM 96
#define W_DIM 96
#define TW 24
#define TH 16
#define PXW 12
#define NPAIR 6
#define NDW 9
#define RAD 4
#define CC 8
#define NSTAGE (C_DIM / CC)                  // 32
#define S1_STRIDE 40
#define S2_STRIDE 40
#define S2_ROWS (TH + 8)                     // 24
#define S1_WORDS (CC * TH * S1_STRIDE)       // 5120
#define S2_WORDS (CC * S2_ROWS * S2_STRIDE)  // 7680
#define STAGE_WORDS (S1_WORDS + S2_WORDS)    // 12800
#define NTHREADS 288
#define N_IN1_CHUNKS (CC * TH * (TW / 4))            // 768
#define N_IN2_CHUNKS (CC * S2_ROWS * ((TW + 8) / 4)) // 1536
#define N_CHUNKS (N_IN1_CHUNKS + N_IN2_CHUNKS)       // 2304
#define CHUNKS_PER_THREAD (N_CHUNKS / NTHREADS)      // 8

typedef unsigned long long u64;

// packed fp32x2 FMA: d.lo += a.lo*b.lo ; d.hi += a.hi*b.hi
__device__ __forceinline__ void fma2(u64 &d, u64 a, u64 b) {
    asm("fma.rn.f32x2 %0, %1, %2, %0;" : "+l"(d) : "l"(a), "l"(b));
}
__device__ __forceinline__ u64 pack2(float lo, float hi) {
    u64 d;
    asm("mov.b64 %0, {%1, %2};" : "=l"(d) : "f"(lo), "f"(hi));
    return d;
}
__device__ __forceinline__ void cp16(uint32_t s, const float* g, bool v) {
    int sz = v ? 16 : 0;
    asm volatile("cp.async.cg.shared.global [%0], [%1], 16, %2;\n"
                 :: "r"(s), "l"(g), "r"(sz));
}

__global__ __launch_bounds__(NTHREADS, 1)
void corr_kernel(const float* __restrict__ in1, const float* __restrict__ in2,
                 float* __restrict__ out) {
    extern __shared__ float smem[];
    const int tid = threadIdx.x;
    const int w0 = blockIdx.x * TW;
    const int h0 = blockIdx.y * TH;
    const int b  = blockIdx.z;

    const int g    = tid >> 5;   // warp id == ph (displacement row), 0..8
    const int lane = tid & 31;
    const int pc   = lane & 1;   // pixel-column block (12 px each)
    const int r    = lane >> 1;  // tile row 0..15

    u64 acc[NPAIR][NDW];
#pragma unroll
    for (int k = 0; k < NPAIR; k++)
#pragma unroll
        for (int d = 0; d < NDW; d++) acc[k][d] = 0ull;

    auto load_stage = [&](int s, int buf) {
        const int c0 = s * CC;
        uint32_t sbase = (uint32_t)__cvta_generic_to_shared(smem + buf * STAGE_WORDS);
#pragma unroll
        for (int j = 0; j < CHUNKS_PER_THREAD; j++) {
            int i = tid + j * NTHREADS;
            if (i < N_IN1_CHUNKS) {
                int c   = i / (TH * (TW / 4));
                int rem = i % (TH * (TW / 4));
                int row = rem / (TW / 4);
                int ch  = rem % (TW / 4);
                const float* gp = in1 +
                    (((size_t)(b * C_DIM + c0 + c) * H_DIM + (h0 + row)) * W_DIM + w0 + ch * 4);
                cp16(sbase + (uint32_t)(((c * TH + row) * S1_STRIDE + ch * 4) * 4), gp, true);
            } else {
                int ii  = i - N_IN1_CHUNKS;
                int c   = ii / (S2_ROWS * 8);
                int rem = ii % (S2_ROWS * 8);
                int row = rem / 8;
                int ch  = rem % 8;
                int h2 = h0 + row - RAD;
                int w2 = w0 + ch * 4 - RAD;
                bool valid = (h2 >= 0) && (h2 < H_DIM) && (w2 >= 0) && (w2 <= W_DIM - 4);
                const float* gp = in2 +
                    (((size_t)(b * C_DIM + c0 + c) * H_DIM + (valid ? h2 : 0)) * W_DIM +
                     (valid ? w2 : 0));
                cp16(sbase + (uint32_t)(S1_WORDS * 4 +
                     ((c * S2_ROWS + row) * S2_STRIDE + ch * 4) * 4), gp, valid);
            }
        }
        asm volatile("cp.async.commit_group;\n");
    };

    load_stage(0, 0);

    for (int s = 0; s < NSTAGE; s++) {
        const int buf = s & 1;
        if (s + 1 < NSTAGE) {
            load_stage(s + 1, (s + 1) & 1);
            asm volatile("cp.async.wait_group 1;\n");
        } else {
            asm volatile("cp.async.wait_group 0;\n");
        }
        __syncthreads();

        const float* s1p = smem + buf * STAGE_WORDS;
        const float* s2p = s1p + S1_WORDS;
#pragma unroll
        for (int cc = 0; cc < CC; cc++) {
            // in1 pixel pairs (aligned 64-bit pairs, loaded as 128-bit LDS)
            const ulonglong2* v1row =
                (const ulonglong2*)(s1p + (cc * TH + r) * S1_STRIDE + pc * PXW);
            u64 v1p[NPAIR];
#pragma unroll
            for (int q = 0; q < 3; q++) {
                ulonglong2 t = v1row[q];
                v1p[2 * q] = t.x; v1p[2 * q + 1] = t.y;
            }
            // in2 row span: 12 px + 8 halo = 20 floats
            const float4* s2row =
                (const float4*)(s2p + (cc * S2_ROWS + (r + g)) * S2_STRIDE + pc * PXW);
            float rr[20];
#pragma unroll
            for (int q = 0; q < 5; q++) {
                float4 t = s2row[q];
                rr[4 * q] = t.x; rr[4 * q + 1] = t.y;
                rr[4 * q + 2] = t.z; rr[4 * q + 3] = t.w;
            }
            u64 e[10], o[9];
#pragma unroll
            for (int j = 0; j < 10; j++) e[j] = pack2(rr[2 * j], rr[2 * j + 1]);
#pragma unroll
            for (int j = 0; j < 9; j++)  o[j] = pack2(rr[2 * j + 1], rr[2 * j + 2]);
#pragma unroll
            for (int k = 0; k < NPAIR; k++)
#pragma unroll
                for (int d = 0; d < NDW; d++) {
                    int st = 2 * k + d;
                    fma2(acc[k][d], v1p[k], (st & 1) ? o[st >> 1] : e[st >> 1]);
                }
        }
        __syncthreads();
    }

    // epilogue: acc pair == (even px, odd px) -> store as 8B
    const size_t plane = (size_t)H_DIM * W_DIM;
    float* op = out + (size_t)(b * 81 + g * 9) * plane +
                (size_t)(h0 + r) * W_DIM + (w0 + pc * PXW);
#pragma unroll
    for (int d = 0; d < NDW; d++) {
        u64* orow = (u64*)(op + (size_t)d * plane);
#pragma unroll
        for (int k = 0; k < NPAIR; k++) orow[k] = acc[k][d];
    }
}

extern "C" void kernel_launch(void* const* d_in, const int* in_sizes, int n_in,
                              void* d_out, int out_size) {
    const float* in1 = (const float*)d_in[0];
    const float* in2 = (const float*)d_in[1];
    float* out = (float*)d_out;
    int Bn = in_sizes[0] / (C_DIM * H_DIM * W_DIM);
    size_t smem_bytes = (size_t)2 * STAGE_WORDS * sizeof(float);  // 102400
    cudaFuncSetAttribute(corr_kernel, cudaFuncAttributeMaxDynamicSharedMemorySize,
                         (int)smem_bytes);
    dim3 grid(W_DIM / TW, H_DIM / TH, Bn);
    corr_kernel<<<grid, NTHREADS, smem_bytes>>>(in1, in2, out);
}

// round 3
// speedup vs baseline: 1.1860x; 1.1860x over previous
#include <cuda_runtime.h>
#include <cstdint>
#include <cstddef>

#define C_DIM 256
#define H_DIM 96
#define W_DIM 96
#define TW 24
#define TH 16
#define NPAIR 3
#define NDW 9
#define RAD 4
#define CC 8
#define NSTAGE (C_DIM / CC)                  // 32
#define S1_STRIDE 36
#define S2_STRIDE 36
#define S2_ROWS (TH + 8)                     // 24
#define S1_WORDS (CC * TH * S1_STRIDE)       // 4608
#define S2_WORDS (CC * S2_ROWS * S2_STRIDE)  // 6912
#define STAGE_WORDS (S1_WORDS + S2_WORDS)    // 11520
#define NTHREADS 576
#define N_IN1_CHUNKS (CC * TH * (TW / 4))            // 768
#define N_IN2_CHUNKS (CC * S2_ROWS * ((TW + 8) / 4)) // 1536
#define N_CHUNKS (N_IN1_CHUNKS + N_IN2_CHUNKS)       // 2304
#define CHUNKS_PER_THREAD (N_CHUNKS / NTHREADS)      // 4

typedef unsigned long long u64;

// packed fp32x2 FMA: d.lo += a.lo*b.lo ; d.hi += a.hi*b.hi
__device__ __forceinline__ void fma2(u64 &d, u64 a, u64 b) {
    asm("fma.rn.f32x2 %0, %1, %2, %0;" : "+l"(d) : "l"(a), "l"(b));
}
__device__ __forceinline__ u64 pack2(float lo, float hi) {
    u64 d;
    asm("mov.b64 %0, {%1, %2};" : "=l"(d) : "f"(lo), "f"(hi));
    return d;
}
__device__ __forceinline__ void unpack2(float &lo, float &hi, u64 v) {
    asm("mov.b64 {%0, %1}, %2;" : "=f"(lo), "=f"(hi) : "l"(v));
}
__device__ __forceinline__ void cp16(uint32_t s, const float* g, bool v) {
    int sz = v ? 16 : 0;
    asm volatile("cp.async.cg.shared.global [%0], [%1], 16, %2;\n"
                 :: "r"(s), "l"(g), "r"(sz));
}

__global__ __launch_bounds__(NTHREADS, 1)
void corr_kernel(const float* __restrict__ in1, const float* __restrict__ in2,
                 float* __restrict__ out) {
    extern __shared__ float smem[];
    const int tid = threadIdx.x;
    const int w0 = blockIdx.x * TW;
    const int h0 = blockIdx.y * TH;
    const int b  = blockIdx.z;

    const int w    = tid >> 5;          // warp 0..17
    const int ph   = w >> 1;            // displacement row 0..8
    const int half = w & 1;             // pixel-column half
    const int lane = tid & 31;
    const int pc   = half * 2 + (lane & 1);  // 6-px block 0..3
    const int r    = lane >> 1;              // tile row 0..15
    const int x0   = pc * 6;

    u64 acc[NPAIR][NDW];
#pragma unroll
    for (int k = 0; k < NPAIR; k++)
#pragma unroll
        for (int d = 0; d < NDW; d++) acc[k][d] = 0ull;

    auto load_stage = [&](int s, int buf) {
        const int c0 = s * CC;
        uint32_t sbase = (uint32_t)__cvta_generic_to_shared(smem + buf * STAGE_WORDS);
#pragma unroll
        for (int j = 0; j < CHUNKS_PER_THREAD; j++) {
            int i = tid + j * NTHREADS;
            if (i < N_IN1_CHUNKS) {
                int c   = i / (TH * (TW / 4));
                int rem = i % (TH * (TW / 4));
                int row = rem / (TW / 4);
                int ch  = rem % (TW / 4);
                const float* gp = in1 +
                    (((size_t)(b * C_DIM + c0 + c) * H_DIM + (h0 + row)) * W_DIM + w0 + ch * 4);
                cp16(sbase + (uint32_t)(((c * TH + row) * S1_STRIDE + ch * 4) * 4), gp, true);
            } else {
                int ii  = i - N_IN1_CHUNKS;
                int c   = ii / (S2_ROWS * 8);
                int rem = ii % (S2_ROWS * 8);
                int row = rem / 8;
                int ch  = rem % 8;
                int h2 = h0 + row - RAD;
                int w2 = w0 + ch * 4 - RAD;
                bool valid = (h2 >= 0) && (h2 < H_DIM) && (w2 >= 0) && (w2 <= W_DIM - 4);
                const float* gp = in2 +
                    (((size_t)(b * C_DIM + c0 + c) * H_DIM + (valid ? h2 : 0)) * W_DIM +
                     (valid ? w2 : 0));
                cp16(sbase + (uint32_t)(S1_WORDS * 4 +
                     ((c * S2_ROWS + row) * S2_STRIDE + ch * 4) * 4), gp, valid);
            }
        }
        asm volatile("cp.async.commit_group;\n");
    };

    load_stage(0, 0);

    for (int s = 0; s < NSTAGE; s++) {
        const int buf = s & 1;
        if (s + 1 < NSTAGE) {
            load_stage(s + 1, (s + 1) & 1);
            asm volatile("cp.async.wait_group 1;\n");
        } else {
            asm volatile("cp.async.wait_group 0;\n");
        }
        __syncthreads();

        const float* s1p = smem + buf * STAGE_WORDS;
        const float* s2p = s1p + S1_WORDS;
#pragma unroll
        for (int cc = 0; cc < CC; cc++) {
            // in1: 3 aligned 64-bit pairs (LDS.64, conflict-free)
            const u64* v1row = (const u64*)(s1p + (cc * TH + r) * S1_STRIDE + x0);
            u64 v1p[NPAIR];
#pragma unroll
            for (int q = 0; q < NPAIR; q++) v1p[q] = v1row[q];

            // in2: 14-float span as 7 LDS.64 -> even pairs e[0..6] directly
            const u64* v2row = (const u64*)(s2p + (cc * S2_ROWS + (r + ph)) * S2_STRIDE + x0);
            u64 e[7];
#pragma unroll
            for (int q = 0; q < 7; q++) e[q] = v2row[q];

            float f[14];
#pragma unroll
            for (int q = 0; q < 7; q++) unpack2(f[2 * q], f[2 * q + 1], e[q]);
            u64 o[6];
#pragma unroll
            for (int q = 0; q < 6; q++) o[q] = pack2(f[2 * q + 1], f[2 * q + 2]);

#pragma unroll
            for (int k = 0; k < NPAIR; k++)
#pragma unroll
                for (int d = 0; d < NDW; d++) {
                    int st = 2 * k + d;
                    fma2(acc[k][d], v1p[k], (st & 1) ? o[st >> 1] : e[st >> 1]);
                }
        }
        __syncthreads();
    }

    // epilogue: acc pair == (even px, odd px) -> 64-bit stores
    const size_t plane = (size_t)H_DIM * W_DIM;
    float* op = out + (size_t)(b * 81 + ph * 9) * plane +
                (size_t)(h0 + r) * W_DIM + (w0 + x0);
#pragma unroll
    for (int d = 0; d < NDW; d++) {
        u64* orow = (u64*)(op + (size_t)d * plane);
#pragma unroll
        for (int k = 0; k < NPAIR; k++) orow[k] = acc[k][d];
    }
}

extern "C" void kernel_launch(void* const* d_in, const int* in_sizes, int n_in,
                              void* d_out, int out_size) {
    const float* in1 = (const float*)d_in[0];
    const float* in2 = (const float*)d_in[1];
    float* out = (float*)d_out;
    int Bn = in_sizes[0] / (C_DIM * H_DIM * W_DIM);
    size_t smem_bytes = (size_t)2 * STAGE_WORDS * sizeof(float);  // 92160
    cudaFuncSetAttribute(corr_kernel, cudaFuncAttributeMaxDynamicSharedMemorySize,
                         (int)smem_bytes);
    dim3 grid(W_DIM / TW, H_DIM / TH, Bn);
    corr_kernel<<<grid, NTHREADS, smem_bytes>>>(in1, in2, out);
}

// round 4
// speedup vs baseline: 1.2088x; 1.0192x over previous
#include <cuda_runtime.h>
#include <cstdint>
#include <cstddef>

#define C_DIM 256
#define H_DIM 96
#define W_DIM 96
#define TW 24
#define TH 8
#define NPAIR 3
#define NDW 9
#define RAD 4
#define CC 8
#define NSTAGE (C_DIM / CC)                  // 32
#define S1_STRIDE 40
#define S2_STRIDE 40
#define S2_ROWS (TH + 8)                     // 16
#define S1_WORDS (CC * TH * S1_STRIDE)       // 2560
#define S2_WORDS (CC * S2_ROWS * S2_STRIDE)  // 5120
#define STAGE_WORDS (S1_WORDS + S2_WORDS)    // 7680
#define NBUF 3
#define NTHREADS 288
#define N_IN1_CHUNKS (CC * TH * (TW / 4))            // 384
#define N_IN2_CHUNKS (CC * S2_ROWS * ((TW + 8) / 4)) // 1024
#define N_CHUNKS (N_IN1_CHUNKS + N_IN2_CHUNKS)       // 1408
#define CHUNKS_PER_THREAD ((N_CHUNKS + NTHREADS - 1) / NTHREADS)  // 5
#define SCRATCH_OFF (NBUF * STAGE_WORDS)     // scratch for inactive-chunk zero fill

typedef unsigned long long u64;

__device__ __forceinline__ void fma2(u64 &d, u64 a, u64 b) {
    asm("fma.rn.f32x2 %0, %1, %2, %0;" : "+l"(d) : "l"(a), "l"(b));
}
__device__ __forceinline__ u64 pack2(float lo, float hi) {
    u64 d;
    asm("mov.b64 %0, {%1, %2};" : "=l"(d) : "f"(lo), "f"(hi));
    return d;
}
__device__ __forceinline__ void unpack2(float &lo, float &hi, u64 v) {
    asm("mov.b64 {%0, %1}, %2;" : "=f"(lo), "=f"(hi) : "l"(v));
}
__device__ __forceinline__ void cp16(uint32_t s, const float* g, bool v) {
    int sz = v ? 16 : 0;
    asm volatile("cp.async.cg.shared.global [%0], [%1], 16, %2;\n"
                 :: "r"(s), "l"(g), "r"(sz));
}

__global__ __launch_bounds__(NTHREADS, 2)
void corr_kernel(const float* __restrict__ in1, const float* __restrict__ in2,
                 float* __restrict__ out) {
    extern __shared__ float smem[];
    const int tid = threadIdx.x;
    const int w0 = blockIdx.x * TW;
    const int h0 = blockIdx.y * TH;
    const int b  = blockIdx.z;

    const int ph   = tid >> 5;          // warp id = displacement row 0..8
    const int lane = tid & 31;
    const int pc   = lane & 3;          // 6-px block 0..3
    const int r    = lane >> 2;         // tile row 0..7
    const int x0   = pc * 6;

    u64 acc[NPAIR][NDW];
#pragma unroll
    for (int k = 0; k < NPAIR; k++)
#pragma unroll
        for (int d = 0; d < NDW; d++) acc[k][d] = 0ull;

    const uint32_t sb0 = (uint32_t)__cvta_generic_to_shared(smem);

    auto load_stage = [&](int s, int buf) {
        const int c0 = s * CC;
        const uint32_t sbase = sb0 + (uint32_t)(buf * STAGE_WORDS * 4);
#pragma unroll
        for (int j = 0; j < CHUNKS_PER_THREAD; j++) {
            int i = tid + j * NTHREADS;
            bool active = (i < N_CHUNKS);
            if (i < N_IN1_CHUNKS) {
                int c   = i / (TH * (TW / 4));
                int rem = i % (TH * (TW / 4));
                int row = rem / (TW / 4);
                int ch  = rem % (TW / 4);
                const float* gp = in1 +
                    (((size_t)(b * C_DIM + c0 + c) * H_DIM + (h0 + row)) * W_DIM + w0 + ch * 4);
                cp16(sbase + (uint32_t)(((c * TH + row) * S1_STRIDE + ch * 4) * 4), gp, true);
            } else {
                int ii  = i - N_IN1_CHUNKS;
                int c   = ii / (S2_ROWS * 8);
                int rem = ii % (S2_ROWS * 8);
                int row = rem / 8;
                int ch  = rem % 8;
                int h2 = h0 + row - RAD;
                int w2 = w0 + ch * 4 - RAD;
                bool valid = active && (h2 >= 0) && (h2 < H_DIM) && (w2 >= 0) && (w2 <= W_DIM - 4);
                const float* gp = in2 +
                    (((size_t)(b * C_DIM + (active ? c0 + c : 0)) * H_DIM + (valid ? h2 : 0)) * W_DIM +
                     (valid ? w2 : 0));
                uint32_t dst = active
                    ? sbase + (uint32_t)(S1_WORDS * 4 + ((c * S2_ROWS + row) * S2_STRIDE + ch * 4) * 4)
                    : sb0 + (uint32_t)(SCRATCH_OFF * 4);
                cp16(dst, gp, valid);
            }
        }
        asm volatile("cp.async.commit_group;\n");
    };

    load_stage(0, 0);
    load_stage(1, 1);

    int bufc = 0;  // compute buffer
    int bufl = 2;  // load buffer (stage s+2)
    for (int s = 0; s < NSTAGE; s++) {
        if (s < NSTAGE - 1) {
            asm volatile("cp.async.wait_group 1;\n");
        } else {
            asm volatile("cp.async.wait_group 0;\n");
        }
        __syncthreads();
        if (s + 2 < NSTAGE) load_stage(s + 2, bufl);

        const float* s1p = smem + bufc * STAGE_WORDS;
        const float* s2p = s1p + S1_WORDS;
#pragma unroll
        for (int cc = 0; cc < CC; cc++) {
            // in1: 3 aligned 64-bit pairs (LDS.64, conflict-free)
            const u64* v1row = (const u64*)(s1p + (cc * TH + r) * S1_STRIDE + x0);
            u64 v1p[NPAIR];
#pragma unroll
            for (int q = 0; q < NPAIR; q++) v1p[q] = v1row[q];

            // in2: 14-float span as 7 LDS.64 -> even pairs directly
            const u64* v2row = (const u64*)(s2p + (cc * S2_ROWS + (r + ph)) * S2_STRIDE + x0);
            u64 e[7];
#pragma unroll
            for (int q = 0; q < 7; q++) e[q] = v2row[q];

            float f[14];
#pragma unroll
            for (int q = 0; q < 7; q++) unpack2(f[2 * q], f[2 * q + 1], e[q]);
            u64 o[6];
#pragma unroll
            for (int q = 0; q < 6; q++) o[q] = pack2(f[2 * q + 1], f[2 * q + 2]);

#pragma unroll
            for (int k = 0; k < NPAIR; k++)
#pragma unroll
                for (int d = 0; d < NDW; d++) {
                    int st = 2 * k + d;
                    fma2(acc[k][d], v1p[k], (st & 1) ? o[st >> 1] : e[st >> 1]);
                }
        }

        bufc = (bufc == NBUF - 1) ? 0 : bufc + 1;
        bufl = (bufl == NBUF - 1) ? 0 : bufl + 1;
    }

    // epilogue: acc pair == (even px, odd px) -> 64-bit stores
    const size_t plane = (size_t)H_DIM * W_DIM;
    float* op = out + (size_t)(b * 81 + ph * 9) * plane +
                (size_t)(h0 + r) * W_DIM + (w0 + x0);
#pragma unroll
    for (int d = 0; d < NDW; d++) {
        u64* orow = (u64*)(op + (size_t)d * plane);
#pragma unroll
        for (int k = 0; k < NPAIR; k++) orow[k] = acc[k][d];
    }
}

extern "C" void kernel_launch(void* const* d_in, const int* in_sizes, int n_in,
                              void* d_out, int out_size) {
    const float* in1 = (const float*)d_in[0];
    const float* in2 = (const float*)d_in[1];
    float* out = (float*)d_out;
    int Bn = in_sizes[0] / (C_DIM * H_DIM * W_DIM);
    size_t smem_bytes = (size_t)(NBUF * STAGE_WORDS + 4) * sizeof(float);  // 92176
    cudaFuncSetAttribute(corr_kernel, cudaFuncAttributeMaxDynamicSharedMemorySize,
                         (int)smem_bytes);
    dim3 grid(W_DIM / TW, H_DIM / TH, Bn);
    corr_kernel<<<grid, NTHREADS, smem_bytes>>>(in1, in2, out);
}

// round 5
// speedup vs baseline: 1.2280x; 1.0158x over previous
#include <cuda_runtime.h>
#include <cstdint>
#include <cstddef>

#define C_DIM 256
#define H_DIM 96
#define W_DIM 96
#define TW 24
#define TH 8
#define NPAIR 3
#define RAD 4
#define CC 8
#define NSTAGE (C_DIM / CC)                  // 32
#define S1_STRIDE 40
#define S2_STRIDE 40
#define S2_ROWS (TH + 8)                     // 16
#define S1_WORDS (CC * TH * S1_STRIDE)       // 2560
#define S2_WORDS (CC * S2_ROWS * S2_STRIDE)  // 5120
#define STAGE_WORDS (S1_WORDS + S2_WORDS)    // 7680
#define NBUF 3
#define NTHREADS 288
#define N_IN1_CHUNKS (CC * TH * (TW / 4))            // 384
#define N_IN2_CHUNKS (CC * S2_ROWS * ((TW + 8) / 4)) // 1024
#define N_CHUNKS (N_IN1_CHUNKS + N_IN2_CHUNKS)       // 1408
#define CHUNKS_PER_THREAD ((N_CHUNKS + NTHREADS - 1) / NTHREADS)  // 5
#define SCRATCH_OFF (NBUF * STAGE_WORDS)

typedef unsigned long long u64;

union F2U { float2 f2; u64 u; };

__device__ __forceinline__ void fma2(u64 &d, u64 a, u64 b) {
    asm("fma.rn.f32x2 %0, %1, %2, %0;" : "+l"(d) : "l"(a), "l"(b));
}
__device__ __forceinline__ void cp16(uint32_t s, const float* g, bool v) {
    int sz = v ? 16 : 0;
    asm volatile("cp.async.cg.shared.global [%0], [%1], 16, %2;\n"
                 :: "r"(s), "l"(g), "r"(sz));
}

__global__ __launch_bounds__(NTHREADS, 2)
void corr_kernel(const float* __restrict__ in1, const float* __restrict__ in2,
                 float* __restrict__ out) {
    extern __shared__ float smem[];
    const int tid = threadIdx.x;
    const int w0 = blockIdx.x * TW;
    const int h0 = blockIdx.y * TH;
    const int b  = blockIdx.z;

    const int ph   = tid >> 5;          // warp id = displacement row 0..8
    const int lane = tid & 31;
    const int pc   = lane & 3;          // 6-px block 0..3
    const int r    = lane >> 2;         // tile row 0..7
    const int x0   = pc * 6;

    // even-dw accumulators: d in {0,2,4,6,8} -> idx d/2
    u64 accE[NPAIR][5];
    // odd-dw accumulators: d in {1,3,5,7} -> idx (d-1)/2 ; [0]=lo px, [1]=hi px
    float accO[NPAIR][4][2];
#pragma unroll
    for (int k = 0; k < NPAIR; k++) {
#pragma unroll
        for (int d = 0; d < 5; d++) accE[k][d] = 0ull;
#pragma unroll
        for (int d = 0; d < 4; d++) { accO[k][d][0] = 0.f; accO[k][d][1] = 0.f; }
    }

    const uint32_t sb0 = (uint32_t)__cvta_generic_to_shared(smem);

    auto load_stage = [&](int s, int buf) {
        const int c0 = s * CC;
        const uint32_t sbase = sb0 + (uint32_t)(buf * STAGE_WORDS * 4);
#pragma unroll
        for (int j = 0; j < CHUNKS_PER_THREAD; j++) {
            int i = tid + j * NTHREADS;
            bool active = (i < N_CHUNKS);
            if (i < N_IN1_CHUNKS) {
                int c   = i / (TH * (TW / 4));
                int rem = i % (TH * (TW / 4));
                int row = rem / (TW / 4);
                int ch  = rem % (TW / 4);
                const float* gp = in1 +
                    (((size_t)(b * C_DIM + c0 + c) * H_DIM + (h0 + row)) * W_DIM + w0 + ch * 4);
                cp16(sbase + (uint32_t)(((c * TH + row) * S1_STRIDE + ch * 4) * 4), gp, true);
            } else {
                int ii  = i - N_IN1_CHUNKS;
                int c   = ii / (S2_ROWS * 8);
                int rem = ii % (S2_ROWS * 8);
                int row = rem / 8;
                int ch  = rem % 8;
                int h2 = h0 + row - RAD;
                int w2 = w0 + ch * 4 - RAD;
                bool valid = active && (h2 >= 0) && (h2 < H_DIM) && (w2 >= 0) && (w2 <= W_DIM - 4);
                const float* gp = in2 +
                    (((size_t)(b * C_DIM + (active ? c0 + c : 0)) * H_DIM + (valid ? h2 : 0)) * W_DIM +
                     (valid ? w2 : 0));
                uint32_t dst = active
                    ? sbase + (uint32_t)(S1_WORDS * 4 + ((c * S2_ROWS + row) * S2_STRIDE + ch * 4) * 4)
                    : sb0 + (uint32_t)(SCRATCH_OFF * 4);
                cp16(dst, gp, valid);
            }
        }
        asm volatile("cp.async.commit_group;\n");
    };

    load_stage(0, 0);
    load_stage(1, 1);

    int bufc = 0;
    int bufl = 2;
    for (int s = 0; s < NSTAGE; s++) {
        if (s < NSTAGE - 1) {
            asm volatile("cp.async.wait_group 1;\n");
        } else {
            asm volatile("cp.async.wait_group 0;\n");
        }
        __syncthreads();
        if (s + 2 < NSTAGE) load_stage(s + 2, bufl);

        const float* s1p = smem + bufc * STAGE_WORDS;
        const float* s2p = s1p + S1_WORDS;
#pragma unroll
        for (int cc = 0; cc < CC; cc++) {
            // in1: 3 aligned float2 (LDS.64, conflict-free)
            const float2* v1row = (const float2*)(s1p + (cc * TH + r) * S1_STRIDE + x0);
            F2U v1[NPAIR];
#pragma unroll
            for (int q = 0; q < NPAIR; q++) v1[q].f2 = v1row[q];

            // in2: 14-float span as 7 aligned float2
            const float2* v2row = (const float2*)(s2p + (cc * S2_ROWS + (r + ph)) * S2_STRIDE + x0);
            F2U v2[7];
#pragma unroll
            for (int q = 0; q < 7; q++) v2[q].f2 = v2row[q];

            // even dw: aligned pair operand, packed FMA (no packing movs)
#pragma unroll
            for (int k = 0; k < NPAIR; k++)
#pragma unroll
                for (int dh = 0; dh < 5; dh++)   // d = 2*dh
                    fma2(accE[k][dh], v1[k].u, v2[k + dh].u);

            // odd dw: straddling pair -> two scalar FMAs on named halves
#pragma unroll
            for (int k = 0; k < NPAIR; k++)
#pragma unroll
                for (int dh = 0; dh < 4; dh++) { // d = 2*dh+1
                    accO[k][dh][0] = __fmaf_rn(v1[k].f2.x, v2[k + dh].f2.y, accO[k][dh][0]);
                    accO[k][dh][1] = __fmaf_rn(v1[k].f2.y, v2[k + dh + 1].f2.x, accO[k][dh][1]);
                }
        }

        bufc = (bufc == NBUF - 1) ? 0 : bufc + 1;
        bufl = (bufl == NBUF - 1) ? 0 : bufl + 1;
    }

    // epilogue
    const size_t plane = (size_t)H_DIM * W_DIM;
    float* op = out + (size_t)(b * 81 + ph * 9) * plane +
                (size_t)(h0 + r) * W_DIM + (w0 + x0);
#pragma unroll
    for (int dh = 0; dh < 5; dh++) {
        u64* orow = (u64*)(op + (size_t)(2 * dh) * plane);
#pragma unroll
        for (int k = 0; k < NPAIR; k++) orow[k] = accE[k][dh];
    }
#pragma unroll
    for (int dh = 0; dh < 4; dh++) {
        float* orow = op + (size_t)(2 * dh + 1) * plane;
#pragma unroll
        for (int k = 0; k < NPAIR; k++) {
            F2U t; t.f2.x = accO[k][dh][0]; t.f2.y = accO[k][dh][1];
            *(u64*)(orow + 2 * k) = t.u;
        }
    }
}

extern "C" void kernel_launch(void* const* d_in, const int* in_sizes, int n_in,
                              void* d_out, int out_size) {
    const float* in1 = (const float*)d_in[0];
    const float* in2 = (const float*)d_in[1];
    float* out = (float*)d_out;
    int Bn = in_sizes[0] / (C_DIM * H_DIM * W_DIM);
    size_t smem_bytes = (size_t)(NBUF * STAGE_WORDS + 4) * sizeof(float);  // 92176
    cudaFuncSetAttribute(corr_kernel, cudaFuncAttributeMaxDynamicSharedMemorySize,
                         (int)smem_bytes);
    dim3 grid(W_DIM / TW, H_DIM / TH, Bn);
    corr_kernel<<<grid, NTHREADS, smem_bytes>>>(in1, in2, out);
}